// round 1
// baseline (speedup 1.0000x reference)
#include <cuda_runtime.h>
#include <cstdint>

#define BATCH   32
#define SEQLEN  4096
#define CIN     7
#define OUTC    512
#define TB      128                  // timesteps per block
#define NT      256                  // threads per block (1 output pair each)
#define WIN     32                   // rotating window slots (>= 24, power of 2, TB % WIN == 0)
#define SROWS   (TB + 24)            // smem rows: g = t0-22 .. t0+129 (last row dead-read only)

// ---------- packed f32x2 helpers ----------
__device__ __forceinline__ unsigned long long pack2(float lo, float hi) {
    unsigned long long r;
    asm("mov.b64 %0, {%1, %2};" : "=l"(r) : "f"(lo), "f"(hi));
    return r;
}
__device__ __forceinline__ void fma2(unsigned long long& acc,
                                     unsigned long long a, unsigned long long b) {
    asm("fma.rn.f32x2 %0, %1, %2, %0;" : "+l"(acc) : "l"(a), "l"(b));
}
__device__ __forceinline__ unsigned long long add2(unsigned long long a, unsigned long long b) {
    unsigned long long r;
    asm("add.rn.f32x2 %0, %1, %2;" : "=l"(r) : "l"(a), "l"(b));
    return r;
}

// Map window offset o = d-22 in [-22, +1] back to (i, j) of the (8,3) kernel.
// o = (j-1) - 3i  ->  i = (1-o)/3 (int div), j = o + 1 + 3i.

__global__ __launch_bounds__(NT, 2)
void conv_main(const float* __restrict__ x, const float* __restrict__ kern,
               float* __restrict__ out) {
    __shared__ float xs[CIN * SROWS];

    const int nt_tiles = SEQLEN / TB;              // 32
    const int b   = blockIdx.x / nt_tiles;
    const int t0  = (blockIdx.x % nt_tiles) * TB;
    const int tid = threadIdx.x;

    // ---- cooperative load of x window (coalesced over gmem) ----
    {
        const float* xb = x + (size_t)b * SEQLEN * CIN;
        for (int idx = tid; idx < CIN * SROWS; idx += NT) {
            int r = idx / CIN;
            int c = idx % CIN;
            int g = t0 - 22 + r;
            float v = 0.0f;
            if (g >= 0 && g < SEQLEN) v = xb[(size_t)g * CIN + c];
            xs[c * SROWS + r] = v;
        }
    }
    __syncthreads();

    // ---- this thread's output pair (o0 even -> aligned STG.64) ----
    const int o0 = 2 * tid;
    const int o1 = o0 + 1;
    const int cA = o0 / 73, kA = o0 % 73;
    int cB, kB;
    if (o1 == 511) { cB = 0; kB = 73; } else { cB = o1 / 73; kB = o1 % 73; }

    // ---- packed weight pairs in registers ----
    unsigned long long wreg[24];
#pragma unroll
    for (int d = 0; d < 24; d++) {
        const int o = d - 22;
        const int i = (1 - o) / 3;
        const int j = o + 1 + 3 * i;
        wreg[d] = pack2(kern[kA * 24 + i * 3 + j], kern[kB * 24 + i * 3 + j]);
    }

    const float* xa = xs + cA * SROWS;
    const float* xb2 = xs + cB * SROWS;

    // ---- rotating register window of packed (xA, xB) values ----
    unsigned long long win[WIN];
#pragma unroll
    for (int d = 0; d < 24; d++)
        win[d] = pack2(xa[d], xb2[d]);

    float* op = out + ((size_t)b * SEQLEN + t0) * OUTC + o0;

    for (int tb = 0; tb < TB; tb += WIN) {
#pragma unroll
        for (int u = 0; u < WIN; u++) {
            const int tl = tb + u;
            // prefetch refill for next iteration into the dead slot
            win[(u + 24) & (WIN - 1)] = pack2(xa[tl + 24], xb2[tl + 24]);

            unsigned long long a0 = 0ull, a1 = 0ull;  // two chains break RAW serialization
#pragma unroll
            for (int d = 0; d < 24; d += 2) {
                fma2(a0, win[(u + d) & (WIN - 1)], wreg[d]);
                fma2(a1, win[(u + d + 1) & (WIN - 1)], wreg[d + 1]);
            }
            const unsigned long long s = add2(a0, a1);
            *reinterpret_cast<unsigned long long*>(op + (size_t)tl * OUTC) = s;
        }
    }
}

// t = L-1 epilogue: the conv's right padding drops all j==2 taps there.
__global__ void conv_fix(const float* __restrict__ x, const float* __restrict__ kern,
                         float* __restrict__ out) {
    const int b = blockIdx.x;
    const int o = threadIdx.x;  // 0..511
    int c, k;
    if (o == 511) { c = 0; k = 73; } else { c = o / 73; k = o % 73; }

    const int t = SEQLEN - 1;
    float s = 0.0f;
#pragma unroll
    for (int i = 0; i < 8; i++) {
#pragma unroll
        for (int j = 0; j < 2; j++) {     // j == 2 excluded by padding at t = L-1
            const int xi = t + j - 1 - 3 * i;
            if (xi >= 0)
                s += x[((size_t)b * SEQLEN + xi) * CIN + c] * kern[k * 24 + i * 3 + j];
        }
    }
    out[((size_t)b * SEQLEN + t) * OUTC + o] = s;
}

extern "C" void kernel_launch(void* const* d_in, const int* in_sizes, int n_in,
                              void* d_out, int out_size) {
    const float* x    = (const float*)d_in[0];   // (32, 4096, 7) f32
    const float* kern = (const float*)d_in[1];   // (74, 8, 3)  f32
    float* out        = (float*)d_out;           // (32, 4096, 512) f32

    conv_main<<<BATCH * (SEQLEN / TB), NT>>>(x, kern, out);
    conv_fix<<<BATCH, OUTC>>>(x, kern, out);     // same stream: ordered after conv_main
}

// round 2
// speedup vs baseline: 1.3742x; 1.3742x over previous
#include <cuda_runtime.h>
#include <cstdint>

#define BATCH   32
#define SEQLEN  4096
#define CIN     7
#define OUTC    512
#define NKERN   74
#define TB      128                  // timesteps per block
#define NT      256                  // threads per block (1 output pair each)
#define T       16                   // output timesteps per accumulator chunk
#define SROWS   (TB + 24)            // smem rows: t0-22 .. t0+TB+1

// ---------- packed f32x2 helpers ----------
__device__ __forceinline__ unsigned long long pack2(float lo, float hi) {
    unsigned long long r;
    asm("mov.b64 %0, {%1, %2};" : "=l"(r) : "f"(lo), "f"(hi));
    return r;
}
__device__ __forceinline__ void fma2(unsigned long long& acc,
                                     unsigned long long a, unsigned long long b) {
    asm("fma.rn.f32x2 %0, %1, %2, %0;" : "+l"(acc) : "l"(a), "l"(b));
}

// Dense 24-tap FIR equivalence: out[b,t,o] = sum_{d=0}^{23} W[o,d] * x[b, t+d-22, c(o)]
// with tap d at offset o = d-22 mapping to kernel (i,j): i = (1-o)/3, j = o+1+3i.

__global__ __launch_bounds__(NT, 2)
void conv_main(const float* __restrict__ x, const float* __restrict__ kern,
               float* __restrict__ out) {
    __shared__ float xs[CIN][SROWS];
    __shared__ float ks[NKERN * 24];

    const int nt_tiles = SEQLEN / TB;              // 32
    const int b   = blockIdx.x / nt_tiles;
    const int t0  = (blockIdx.x % nt_tiles) * TB;
    const int tid = threadIdx.x;

    // ---- cooperative loads: x window + all kernel weights ----
    {
        const float* xb = x + (size_t)b * SEQLEN * CIN;
        for (int idx = tid; idx < CIN * SROWS; idx += NT) {
            int r = idx / CIN;
            int c = idx % CIN;
            int g = t0 - 22 + r;
            float v = 0.0f;
            if (g >= 0 && g < SEQLEN) v = xb[(size_t)g * CIN + c];
            xs[c][r] = v;
        }
        for (int idx = tid; idx < NKERN * 24; idx += NT)
            ks[idx] = kern[idx];
    }
    __syncthreads();

    // ---- this thread's output pair (o0 even -> aligned STG.64) ----
    const int o0 = 2 * tid;
    const int o1 = o0 + 1;
    const int cA = o0 / 73, kA = o0 % 73;
    int cB, kB;
    if (o1 == 511) { cB = 0; kB = 73; } else { cB = o1 / 73; kB = o1 % 73; }

    // ---- packed weight pairs in registers (48 regs) ----
    unsigned long long wreg[24];
#pragma unroll
    for (int d = 0; d < 24; d++) {
        const int o = d - 22;
        const int i = (1 - o) / 3;
        const int j = o + 1 + 3 * i;
        wreg[d] = pack2(ks[kA * 24 + i * 3 + j], ks[kB * 24 + i * 3 + j]);
    }

    const float* xa = xs[cA];
    const float* xb2 = xs[cB];
    float* op = out + ((size_t)b * SEQLEN + t0) * OUTC + o0;

    // ---- streaming-accumulator FIR: T outputs per chunk, x streams through 1 reg ----
#pragma unroll 1
    for (int cbase = 0; cbase < TB; cbase += T) {
        unsigned long long acc[T];
#pragma unroll
        for (int tr = 0; tr < T; tr++) acc[tr] = 0ull;

#pragma unroll
        for (int gg = 0; gg < T + 23; gg++) {
            const int row = cbase + gg;               // = (t_local - 22) + 22 offset folded
            const unsigned long long px = pack2(xa[row], xb2[row]);
#pragma unroll
            for (int tr = 0; tr < T; tr++) {
                const int d = gg - tr;                // tap index, compile-time per (gg,tr)
                if (d >= 0 && d < 24) fma2(acc[tr], px, wreg[d]);
            }
        }

        float* opc = op + (size_t)cbase * OUTC;
#pragma unroll
        for (int tr = 0; tr < T; tr++)
            *reinterpret_cast<unsigned long long*>(opc + (size_t)tr * OUTC) = acc[tr];
    }

    // ---- folded t = L-1 fix: right padding kills ALL j==2 taps there ----
    // Same thread re-stores its own pair -> program-ordered WAW, no sync needed.
    if (t0 + TB == SEQLEN) {
        const int row = TB + 21;                      // local row of t = L-1
        float sA = 0.0f, sB = 0.0f;
#pragma unroll
        for (int i = 0; i < 8; i++) {
#pragma unroll
            for (int j = 0; j < 2; j++) {
                const int r = row + (j - 1) - 3 * i;  // >= row-22 >= 0
                sA += xa[r] * ks[kA * 24 + i * 3 + j];
                sB += xb2[r] * ks[kB * 24 + i * 3 + j];
            }
        }
        *reinterpret_cast<unsigned long long*>(op + (size_t)(TB - 1) * OUTC) = pack2(sA, sB);
    }
}

extern "C" void kernel_launch(void* const* d_in, const int* in_sizes, int n_in,
                              void* d_out, int out_size) {
    const float* x    = (const float*)d_in[0];   // (32, 4096, 7) f32
    const float* kern = (const float*)d_in[1];   // (74, 8, 3)  f32
    float* out        = (float*)d_out;           // (32, 4096, 512) f32

    conv_main<<<BATCH * (SEQLEN / TB), NT>>>(x, kern, out);
}